// round 1
// baseline (speedup 1.0000x reference)
#include <cuda_runtime.h>
#include <cstdint>

#define T_    4
#define B_    32
#define C_    384
#define HID_  1536
#define HW_   196
#define NPAIR (B_*HW_)        // 6272 (b,hw) pairs
#define NROW  (NPAIR*T_)      // 25088 rows of GEMM1
#define CW_   (C_/32)         // 12 bitmask words per row
#define SPIKE_CAP (1u<<22)

#define PG 64                 // pairs per CTA in fused kernel
#define ON 128                // output-channel chunk
#define NCH (HID_/ON)         // 12
#define NG  (NPAIR/PG)        // 98

// ---- scratch (static device allocations; no cudaMalloc anywhere) ----
__device__ float          g_w1t[C_*HID_];        // [c][o]   2.36 MB
__device__ float          g_w2t[HID_*C_];        // [c][o]   2.36 MB
__device__ unsigned       g_smask[NROW*CW_];     // s1 bitmasks
__device__ unsigned short g_list[(size_t)NROW*C_]; // per-row active-c lists
__device__ int            g_cnt[NROW];
__device__ unsigned       g_spikes[SPIKE_CAP];
__device__ unsigned       g_nspk;

// ---------------- K0: 32x32 tiled transpose ----------------
__global__ void k_transpose(const float* __restrict__ in, float* __restrict__ outp,
                            int rows, int cols) {
    __shared__ float tile[32][33];
    int bx = blockIdx.x * 32, by = blockIdx.y * 32;
    int x = bx + threadIdx.x;
    #pragma unroll
    for (int k = 0; k < 32; k += 8) {
        int y = by + threadIdx.y + k;
        if (x < cols && y < rows)
            tile[threadIdx.y + k][threadIdx.x] = in[(size_t)y*cols + x];
    }
    __syncthreads();
    int xo = by + threadIdx.x;          // new col = old row
    #pragma unroll
    for (int k = 0; k < 32; k += 8) {
        int yo = bx + threadIdx.y + k;  // new row = old col
        if (xo < rows && yo < cols)
            outp[(size_t)yo*rows + xo] = tile[threadIdx.x][threadIdx.y + k];
    }
}

// ---------------- K1: PLIF1 -> spike bitmasks ----------------
// thread = (cword, pair); each thread runs the 4-step LIF for 32 channels.
__global__ void k_plif1(const float* __restrict__ x, const float* __restrict__ pw1) {
    int tid = blockIdx.x * blockDim.x + threadIdx.x;
    if (tid == 0) g_nspk = 0u;                 // reset spike counter every launch
    if (tid >= CW_ * NPAIR) return;
    int pair = tid % NPAIR;
    int cw   = tid / NPAIR;
    int b = pair / HW_, hw = pair % HW_;
    float decay = 1.0f / (1.0f + expf(-pw1[0]));

    unsigned bits[T_] = {0u, 0u, 0u, 0u};
    #pragma unroll 4
    for (int j = 0; j < 32; j++) {
        int c = cw * 32 + j;
        const float* xp = x + ((size_t)b * C_ + c) * HW_ + hw;
        float x0 = __ldg(xp);
        float x1 = __ldg(xp + (size_t)1*B_*C_*HW_);
        float x2 = __ldg(xp + (size_t)2*B_*C_*HW_);
        float x3 = __ldg(xp + (size_t)3*B_*C_*HW_);
        float v = 0.f, h;
        h = v + (x0 - v) * decay; if (h >= 1.0f) { bits[0] |= 1u << j; v = 0.f; } else v = h;
        h = v + (x1 - v) * decay; if (h >= 1.0f) { bits[1] |= 1u << j; v = 0.f; } else v = h;
        h = v + (x2 - v) * decay; if (h >= 1.0f) { bits[2] |= 1u << j; v = 0.f; } else v = h;
        h = v + (x3 - v) * decay; if (h >= 1.0f) { bits[3] |= 1u << j; v = 0.f; } else v = h;
    }
    int rbase = pair * T_;
    #pragma unroll
    for (int t = 0; t < T_; t++)
        g_smask[(rbase + t) * CW_ + cw] = bits[t];
}

// ---------------- K2: bitmask -> ordered active-channel lists ----------------
__global__ void k_listbuild() {
    int wrow = (blockIdx.x * blockDim.x + threadIdx.x) >> 5;
    int lane = threadIdx.x & 31;
    if (wrow >= NROW) return;
    unsigned short* lp = g_list + (size_t)wrow * C_;
    int base = 0;
    #pragma unroll
    for (int w = 0; w < CW_; w++) {
        unsigned word = g_smask[wrow * CW_ + w];
        if ((word >> lane) & 1u) {
            int pre = __popc(word & ((1u << lane) - 1u));
            lp[base + pre] = (unsigned short)(w * 32 + lane);
        }
        base += __popc(word);
    }
    if (lane == 0) g_cnt[wrow] = base;
}

// ---------------- K3: fused sparse GEMM1 + PLIF2 -> spike list ----------------
__device__ __forceinline__ void plif2_comp(float a, float bb, float& v, float decay,
                                           int t, int b, int hw, int o) {
    float xx = a + bb;
    float h = v + (xx - v) * decay;
    if (h >= 1.0f) {
        unsigned pos = atomicAdd(&g_nspk, 1u);
        if (pos < SPIKE_CAP)
            g_spikes[pos] = (unsigned)((((t * B_ + b) * HID_) + o) * HW_ + hw);
        v = 0.f;
    } else {
        v = h;
    }
}

__global__ __launch_bounds__(512, 1)
void k_gemm1_plif2(const float* __restrict__ pw2, const float* __restrict__ b1) {
    extern __shared__ float ws[];              // [C_][ON] f32 = 196608 B
    const int chunk = blockIdx.x;              // 0..NCH-1
    const int g     = blockIdx.y;              // 0..NG-1
    const int tid   = threadIdx.x;

    // stage w1t[:, chunk*ON : +ON] into smem (float4, fully coalesced)
    const float* w1tp = g_w1t + chunk * ON;
    for (int i = tid; i < C_ * (ON/4); i += 512) {
        int c  = i >> 5;                       // ON/4 = 32
        int o4 = i & 31;
        ((float4*)ws)[i] = __ldg((const float4*)(w1tp + (size_t)c * HID_) + o4);
    }
    __syncthreads();

    const int warp = tid >> 5, oq = tid & 31;
    const float4* ws4 = (const float4*)ws;

    float4 acc[4][T_];
    #pragma unroll
    for (int p = 0; p < 4; p++)
        #pragma unroll
        for (int t = 0; t < T_; t++) acc[p][t] = make_float4(0.f, 0.f, 0.f, 0.f);

    const int pair0 = g * PG + warp * 4;       // 4 pairs per warp

    #pragma unroll
    for (int p = 0; p < 4; p++) {
        const int pair = pair0 + p;
        #pragma unroll
        for (int t = 0; t < T_; t++) {
            const int row = pair * T_ + t;
            const int n = g_cnt[row];
            const unsigned short* lp = g_list + (size_t)row * C_;
            float4 a = acc[p][t];
            int i = 0;
            for (; i + 4 <= n; i += 4) {
                ushort4 cc = *(const ushort4*)(lp + i);   // 8B-aligned uniform load
                float4 v0 = ws4[cc.x * 32 + oq];
                float4 v1 = ws4[cc.y * 32 + oq];
                float4 v2 = ws4[cc.z * 32 + oq];
                float4 v3 = ws4[cc.w * 32 + oq];
                a.x += v0.x; a.y += v0.y; a.z += v0.z; a.w += v0.w;
                a.x += v1.x; a.y += v1.y; a.z += v1.z; a.w += v1.w;
                a.x += v2.x; a.y += v2.y; a.z += v2.z; a.w += v2.w;
                a.x += v3.x; a.y += v3.y; a.z += v3.z; a.w += v3.w;
            }
            for (; i < n; i++) {
                float4 v0 = ws4[(int)lp[i] * 32 + oq];
                a.x += v0.x; a.y += v0.y; a.z += v0.z; a.w += v0.w;
            }
            acc[p][t] = a;
        }
    }

    // epilogue: PLIF2 across t (exact fp32), emit rare spikes
    const float decay = 1.0f / (1.0f + expf(-pw2[0]));
    const float4 b1v = __ldg((const float4*)(b1 + chunk * ON) + oq);
    const int obase = chunk * ON + oq * 4;
    #pragma unroll
    for (int p = 0; p < 4; p++) {
        const int pair = pair0 + p;
        const int b = pair / HW_, hw = pair % HW_;
        float vx = 0.f, vy = 0.f, vz = 0.f, vw = 0.f;
        #pragma unroll
        for (int t = 0; t < T_; t++) {
            plif2_comp(acc[p][t].x, b1v.x, vx, decay, t, b, hw, obase + 0);
            plif2_comp(acc[p][t].y, b1v.y, vy, decay, t, b, hw, obase + 1);
            plif2_comp(acc[p][t].z, b1v.z, vz, decay, t, b, hw, obase + 2);
            plif2_comp(acc[p][t].w, b1v.w, vw, decay, t, b, hw, obase + 3);
        }
    }
}

// ---------------- K4: out = b2 (broadcast fill) ----------------
__global__ void k_outinit(float* __restrict__ out, const float* __restrict__ b2) {
    int i = blockIdx.x * blockDim.x + threadIdx.x;   // float4 index
    const int total4 = T_ * B_ * C_ * HW_ / 4;
    if (i >= total4) return;
    int o = (i / (HW_ / 4)) % C_;
    float bv = __ldg(b2 + o);
    ((float4*)out)[i] = make_float4(bv, bv, bv, bv);
}

// ---------------- K5: scatter spikes -> out += w2t column ----------------
__global__ void k_scatter(float* __restrict__ out) {
    unsigned n = *(volatile unsigned*)&g_nspk;
    if (n > SPIKE_CAP) n = SPIKE_CAP;
    int wid  = (blockIdx.x * blockDim.x + threadIdx.x) >> 5;
    int lane = threadIdx.x & 31;
    int nw   = (gridDim.x * blockDim.x) >> 5;
    for (unsigned s = wid; s < n; s += nw) {
        unsigned lin = g_spikes[s];
        unsigned hw = lin % HW_;
        unsigned r  = lin / HW_;
        unsigned c  = r % HID_;          // hidden channel that spiked
        unsigned tb = r / HID_;          // t*B + b
        const float* wcol = g_w2t + (size_t)c * C_;
        float* op = out + (size_t)tb * C_ * HW_ + hw;
        for (int o = lane; o < C_; o += 32)
            atomicAdd(op + (size_t)o * HW_, wcol[o]);
    }
}

// ---------------- launch ----------------
extern "C" void kernel_launch(void* const* d_in, const int* in_sizes, int n_in,
                              void* d_out, int out_size) {
    const float* x   = (const float*)d_in[0];
    const float* pw1 = (const float*)d_in[1];
    const float* w1  = (const float*)d_in[2];
    const float* b1  = (const float*)d_in[3];
    const float* pw2 = (const float*)d_in[4];
    const float* w2  = (const float*)d_in[5];
    const float* b2  = (const float*)d_in[6];
    float* out = (float*)d_out;

    (void)in_sizes; (void)n_in; (void)out_size;

    cudaFuncSetAttribute(k_gemm1_plif2,
                         cudaFuncAttributeMaxDynamicSharedMemorySize, C_ * ON * 4);

    float* w1t; cudaGetSymbolAddress((void**)&w1t, g_w1t);
    float* w2t; cudaGetSymbolAddress((void**)&w2t, g_w2t);

    {   // w1 [HID_,C_] -> w1t [C_,HID_]
        dim3 blk(32, 8), grd(C_ / 32, HID_ / 32);
        k_transpose<<<grd, blk>>>(w1, w1t, HID_, C_);
    }
    {   // w2 [C_,HID_] -> w2t [HID_,C_]
        dim3 blk(32, 8), grd(HID_ / 32, C_ / 32);
        k_transpose<<<grd, blk>>>(w2, w2t, C_, HID_);
    }

    k_plif1<<<(CW_ * NPAIR + 255) / 256, 256>>>(x, pw1);
    k_listbuild<<<(NROW * 32 + 255) / 256, 256>>>();

    dim3 g2(NCH, NG);
    k_gemm1_plif2<<<g2, 512, C_ * ON * 4>>>(pw2, b1);

    k_outinit<<<(T_ * B_ * C_ * HW_ / 4 + 255) / 256, 256>>>(out, b2);
    k_scatter<<<256, 256>>>(out);
}